// round 2
// baseline (speedup 1.0000x reference)
#include <cuda_runtime.h>

// Problem constants
#define BATCH 16
#define CDIM  256      // channels (= dim = heads*dim_head)
#define NPix  4096     // h*w
#define HEADS 4
#define DH    64
#define O3    768      // 3 * hidden
#define NSPLIT 16      // split-K factor for context contraction

// Scratch (allocation-free rule: __device__ globals)
__device__ float g_qkv[(size_t)BATCH * O3 * NPix];              // ~201 MB
__device__ float g_ctxp[(size_t)NSPLIT * BATCH * HEADS * DH * DH]; // 16 MB partials
__device__ float g_M[(size_t)BATCH * CDIM * CDIM];              // 4 MB

// ---------------------------------------------------------------------------
// Kernel 1: qkv[b,o,n] = sum_c W[o,c] * x[b,c,n]
// 64x64 block tile, BK=16, 256 threads, 4x4 micro-tile
// ---------------------------------------------------------------------------
__global__ __launch_bounds__(256) void k_qkv(const float* __restrict__ W,
                                             const float* __restrict__ X) {
    __shared__ float As[16][64];   // [c][o]  (transposed)
    __shared__ float Bs[16][68];   // [c][n]  (padded)

    const int b  = blockIdx.z;
    const int o0 = blockIdx.y * 64;
    const int n0 = blockIdx.x * 64;
    const float* Xb = X + (size_t)b * CDIM * NPix;
    float*       Cb = g_qkv + (size_t)b * O3 * NPix;

    const int tid = threadIdx.x;
    const int tx = tid & 15;       // n micro
    const int ty = tid >> 4;       // o micro

    float acc[4][4] = {};

    for (int c0 = 0; c0 < CDIM; c0 += 16) {
        // Load W tile 64(o) x 16(c), store transposed
        {
            int row = tid >> 2;            // 0..63  (o)
            int col = (tid & 3) * 4;       // 0,4,8,12 (c)
            float4 a = *(const float4*)&W[(size_t)(o0 + row) * CDIM + c0 + col];
            As[col + 0][row] = a.x;
            As[col + 1][row] = a.y;
            As[col + 2][row] = a.z;
            As[col + 3][row] = a.w;
        }
        // Load X tile 16(c) x 64(n)
        {
            int row = tid >> 4;            // 0..15 (c)
            int col = (tid & 15) * 4;      // 0..60 (n)
            float4 v = *(const float4*)&Xb[(size_t)(c0 + row) * NPix + n0 + col];
            *(float4*)&Bs[row][col] = v;
        }
        __syncthreads();
        #pragma unroll
        for (int kk = 0; kk < 16; kk++) {
            float4 a = *(const float4*)&As[kk][ty * 4];
            float4 bv = *(const float4*)&Bs[kk][tx * 4];
            float av[4] = {a.x, a.y, a.z, a.w};
            float bb[4] = {bv.x, bv.y, bv.z, bv.w};
            #pragma unroll
            for (int i = 0; i < 4; i++)
                #pragma unroll
                for (int j = 0; j < 4; j++)
                    acc[i][j] = fmaf(av[i], bb[j], acc[i][j]);
        }
        __syncthreads();
    }
    #pragma unroll
    for (int i = 0; i < 4; i++) {
        float4 v = make_float4(acc[i][0], acc[i][1], acc[i][2], acc[i][3]);
        *(float4*)&Cb[(size_t)(o0 + ty * 4 + i) * NPix + n0 + tx * 4] = v;
    }
}

// ---------------------------------------------------------------------------
// Kernel 2: softmax over n for the K rows (rows [256, 512) of each batch)
// one block (256 threads) per row
// ---------------------------------------------------------------------------
__global__ __launch_bounds__(256) void k_softmax() {
    const int r  = blockIdx.x;        // 0 .. BATCH*256-1
    const int b  = r >> 8;
    const int hr = r & 255;
    float* p = g_qkv + (size_t)b * O3 * NPix + (size_t)(CDIM + hr) * NPix;

    __shared__ float red[256];
    const int tid = threadIdx.x;

    float m = -1e30f;
    for (int i = tid; i < NPix; i += 256) m = fmaxf(m, p[i]);
    red[tid] = m; __syncthreads();
    for (int s = 128; s > 0; s >>= 1) {
        if (tid < s) red[tid] = fmaxf(red[tid], red[tid + s]);
        __syncthreads();
    }
    m = red[0];
    __syncthreads();

    float sum = 0.f;
    for (int i = tid; i < NPix; i += 256) sum += __expf(p[i] - m);
    red[tid] = sum; __syncthreads();
    for (int s = 128; s > 0; s >>= 1) {
        if (tid < s) red[tid] += red[tid + s];
        __syncthreads();
    }
    const float inv = 1.0f / red[0];
    for (int i = tid; i < NPix; i += 256) p[i] = __expf(p[i] - m) * inv;
}

// ---------------------------------------------------------------------------
// Kernel 3: partial context. ctxp[s][b,h,d,e] = sum_{n in slice s} k[d,n]*v[e,n]
// grid (NSPLIT, BATCH*HEADS), 256 threads, 4x4 micro-tile over 64x64 output
// ---------------------------------------------------------------------------
__global__ __launch_bounds__(256) void k_ctx() {
    const int split = blockIdx.x;
    const int bh = blockIdx.y;
    const int b = bh >> 2;
    const int h = bh & 3;
    const float* kp = g_qkv + (size_t)b * O3 * NPix + (size_t)(CDIM + h * DH) * NPix;
    const float* vp = g_qkv + (size_t)b * O3 * NPix + (size_t)(2 * CDIM + h * DH) * NPix;

    __shared__ float Ks[64][65];
    __shared__ float Vs[64][65];

    const int tid = threadIdx.x;
    const int tx = tid & 15;    // e micro
    const int ty = tid >> 4;    // d micro

    float acc[4][4] = {};

    const int nbeg = split * (NPix / NSPLIT);
    const int nend = nbeg + (NPix / NSPLIT);

    for (int n0 = nbeg; n0 < nend; n0 += 64) {
        #pragma unroll
        for (int i = 0; i < 16; i++) {
            int idx = tid + i * 256;
            int row = idx >> 6;
            int col = idx & 63;
            Ks[row][col] = kp[(size_t)row * NPix + n0 + col];
            Vs[row][col] = vp[(size_t)row * NPix + n0 + col];
        }
        __syncthreads();
        #pragma unroll 8
        for (int nn = 0; nn < 64; nn++) {
            float av[4], bb[4];
            #pragma unroll
            for (int i = 0; i < 4; i++) av[i] = Ks[ty * 4 + i][nn];
            #pragma unroll
            for (int j = 0; j < 4; j++) bb[j] = Vs[tx * 4 + j][nn];
            #pragma unroll
            for (int i = 0; i < 4; i++)
                #pragma unroll
                for (int j = 0; j < 4; j++)
                    acc[i][j] = fmaf(av[i], bb[j], acc[i][j]);
        }
        __syncthreads();
    }

    float* cp = g_ctxp + ((size_t)split * (BATCH * HEADS) + bh) * (DH * DH);
    #pragma unroll
    for (int i = 0; i < 4; i++)
        #pragma unroll
        for (int j = 0; j < 4; j++)
            cp[(size_t)(ty * 4 + i) * DH + tx * 4 + j] = acc[i][j];
}

// ---------------------------------------------------------------------------
// Kernel 4: M[b][o][h*64+d] = gamma[o] * sum_e w_out[o][h*64+e] * ctx[b,h,d,e]
// one block per (b,h); thread = o
// ---------------------------------------------------------------------------
__global__ __launch_bounds__(256) void k_mix(const float* __restrict__ Wout,
                                             const float* __restrict__ gamma) {
    const int bh = blockIdx.x;
    const int b = bh >> 2;
    const int h = bh & 3;

    __shared__ float cs[64][65];
    const int tid = threadIdx.x;

    // Reduce the NSPLIT partials into smem
    for (int idx = tid; idx < DH * DH; idx += 256) {
        float s = 0.f;
        #pragma unroll
        for (int sp = 0; sp < NSPLIT; sp++)
            s += g_ctxp[((size_t)sp * (BATCH * HEADS) + bh) * (DH * DH) + idx];
        cs[idx >> 6][idx & 63] = s;
    }
    __syncthreads();

    const int o = tid;
    float acc[64];
    #pragma unroll
    for (int d = 0; d < 64; d++) acc[d] = 0.f;

    for (int e = 0; e < 64; e++) {
        const float w = Wout[(size_t)o * CDIM + h * DH + e];
        #pragma unroll
        for (int d = 0; d < 64; d++)
            acc[d] = fmaf(w, cs[d][e], acc[d]);
    }
    const float g = gamma[o];
    float* mp = g_M + ((size_t)b * CDIM + o) * CDIM + h * DH;
    #pragma unroll
    for (int d = 0; d < 64; d++) mp[d] = g * acc[d];
}

// ---------------------------------------------------------------------------
// Kernel 5: y[b,o,n] = sum_c M[b][o][c] * q[b,c,n] + gamma[o]*b_out[o] + x[b,o,n]
// same tiling as kernel 1, fused epilogue
// ---------------------------------------------------------------------------
__global__ __launch_bounds__(256) void k_out(const float* __restrict__ X,
                                             const float* __restrict__ b_out,
                                             const float* __restrict__ gamma,
                                             float* __restrict__ Y) {
    __shared__ float As[16][64];
    __shared__ float Bs[16][68];

    const int b  = blockIdx.z;
    const int o0 = blockIdx.y * 64;
    const int n0 = blockIdx.x * 64;
    const float* Mb = g_M + (size_t)b * CDIM * CDIM;
    const float* Qb = g_qkv + (size_t)b * O3 * NPix;        // q = rows [0,256)
    const float* Xb = X + (size_t)b * CDIM * NPix;
    float*       Yb = Y + (size_t)b * CDIM * NPix;

    const int tid = threadIdx.x;
    const int tx = tid & 15;
    const int ty = tid >> 4;

    float acc[4][4] = {};

    for (int c0 = 0; c0 < CDIM; c0 += 16) {
        {
            int row = tid >> 2;
            int col = (tid & 3) * 4;
            float4 a = *(const float4*)&Mb[(size_t)(o0 + row) * CDIM + c0 + col];
            As[col + 0][row] = a.x;
            As[col + 1][row] = a.y;
            As[col + 2][row] = a.z;
            As[col + 3][row] = a.w;
        }
        {
            int row = tid >> 4;
            int col = (tid & 15) * 4;
            float4 v = *(const float4*)&Qb[(size_t)(c0 + row) * NPix + n0 + col];
            *(float4*)&Bs[row][col] = v;
        }
        __syncthreads();
        #pragma unroll
        for (int kk = 0; kk < 16; kk++) {
            float4 a = *(const float4*)&As[kk][ty * 4];
            float4 bv = *(const float4*)&Bs[kk][tx * 4];
            float av[4] = {a.x, a.y, a.z, a.w};
            float bb[4] = {bv.x, bv.y, bv.z, bv.w};
            #pragma unroll
            for (int i = 0; i < 4; i++)
                #pragma unroll
                for (int j = 0; j < 4; j++)
                    acc[i][j] = fmaf(av[i], bb[j], acc[i][j]);
        }
        __syncthreads();
    }

    #pragma unroll
    for (int i = 0; i < 4; i++) {
        const int o = o0 + ty * 4 + i;
        const float bias = gamma[o] * b_out[o];
        const size_t off = (size_t)o * NPix + n0 + tx * 4;
        float4 xv = *(const float4*)&Xb[off];
        float4 v = make_float4(acc[i][0] + bias + xv.x,
                               acc[i][1] + bias + xv.y,
                               acc[i][2] + bias + xv.z,
                               acc[i][3] + bias + xv.w);
        *(float4*)&Yb[off] = v;
    }
}

// ---------------------------------------------------------------------------
extern "C" void kernel_launch(void* const* d_in, const int* in_sizes, int n_in,
                              void* d_out, int out_size) {
    const float* x      = (const float*)d_in[0];
    const float* w_qkv  = (const float*)d_in[1];
    const float* w_out  = (const float*)d_in[2];
    const float* b_out  = (const float*)d_in[3];
    const float* gamma  = (const float*)d_in[4];
    float* y = (float*)d_out;

    k_qkv<<<dim3(NPix / 64, O3 / 64, BATCH), 256>>>(w_qkv, x);
    k_softmax<<<BATCH * HEADS * DH, 256>>>();
    k_ctx<<<dim3(NSPLIT, BATCH * HEADS), 256>>>();
    k_mix<<<BATCH * HEADS, 256>>>(w_out, gamma);
    k_out<<<dim3(NPix / 64, CDIM / 64, BATCH), 256>>>(x, b_out, gamma, y);
}

// round 4
// speedup vs baseline: 3.7716x; 3.7716x over previous
#include <cuda_runtime.h>
#include <cuda_bf16.h>
#include <cstdint>

// Problem constants
#define BATCH 16
#define CDIM  256
#define NPix  4096
#define HEADS 4
#define DH    64
#define O3    768
#define NSPLIT 8

// Scratch (__device__ globals: allocation-free rule)
__device__ __nv_bfloat16 g_qkv[(size_t)BATCH * O3 * NPix];     // 100 MB
__device__ __nv_bfloat16 g_xb [(size_t)BATCH * CDIM * NPix];   // 33 MB
__device__ __nv_bfloat16 g_wq [(size_t)O3 * CDIM];             // 384 KB
__device__ float g_ctxp[(size_t)NSPLIT * BATCH * HEADS * DH * DH]; // 8 MB
__device__ __nv_bfloat16 g_M[(size_t)BATCH * CDIM * CDIM];     // 2 MB

__device__ __forceinline__ uint32_t cvta_s(const void* p) {
    return (uint32_t)__cvta_generic_to_shared(p);
}

#define LDSM_X4(r0,r1,r2,r3,addr) \
    asm volatile("ldmatrix.sync.aligned.m8n8.x4.shared.b16 {%0,%1,%2,%3}, [%4];" \
                 : "=r"(r0),"=r"(r1),"=r"(r2),"=r"(r3) : "r"(addr))
#define LDSM_X4_T(r0,r1,r2,r3,addr) \
    asm volatile("ldmatrix.sync.aligned.m8n8.x4.trans.shared.b16 {%0,%1,%2,%3}, [%4];" \
                 : "=r"(r0),"=r"(r1),"=r"(r2),"=r"(r3) : "r"(addr))
#define MMA_BF16(c,a,b0,b1) \
    asm volatile("mma.sync.aligned.m16n8k16.row.col.f32.bf16.bf16.f32 " \
                 "{%0,%1,%2,%3},{%4,%5,%6,%7},{%8,%9},{%0,%1,%2,%3};" \
                 : "+f"((c)[0]),"+f"((c)[1]),"+f"((c)[2]),"+f"((c)[3]) \
                 : "r"((a)[0]),"r"((a)[1]),"r"((a)[2]),"r"((a)[3]),"r"(b0),"r"(b1))

// ---------------------------------------------------------------------------
// Conversion kernels (fp32 -> bf16)
// ---------------------------------------------------------------------------
__global__ __launch_bounds__(256) void k_cvt_x(const float* __restrict__ x) {
    size_t i = ((size_t)blockIdx.x * 256 + threadIdx.x) * 4;
    float4 v = *(const float4*)&x[i];
    __nv_bfloat162 lo, hi;
    lo.x = __float2bfloat16_rn(v.x); lo.y = __float2bfloat16_rn(v.y);
    hi.x = __float2bfloat16_rn(v.z); hi.y = __float2bfloat16_rn(v.w);
    *(__nv_bfloat162*)&g_xb[i]     = lo;
    *(__nv_bfloat162*)&g_xb[i + 2] = hi;
}
__global__ __launch_bounds__(256) void k_cvt_w(const float* __restrict__ w) {
    size_t i = ((size_t)blockIdx.x * 256 + threadIdx.x) * 4;
    float4 v = *(const float4*)&w[i];
    __nv_bfloat162 lo, hi;
    lo.x = __float2bfloat16_rn(v.x); lo.y = __float2bfloat16_rn(v.y);
    hi.x = __float2bfloat16_rn(v.z); hi.y = __float2bfloat16_rn(v.w);
    *(__nv_bfloat162*)&g_wq[i]     = lo;
    *(__nv_bfloat162*)&g_wq[i + 2] = hi;
}

// ---------------------------------------------------------------------------
// Kernel 1: qkv[b,o,n] = sum_c W[o,c]*x[b,c,n]  (bf16 HMMA, 128x128x32 tiles)
// ---------------------------------------------------------------------------
__global__ __launch_bounds__(256) void k_qkv() {
    __shared__ __nv_bfloat16 As[128][40];    // [o][c]
    __shared__ __nv_bfloat16 Bs[32][136];    // [c][n]

    const int b  = blockIdx.z;
    const int o0 = blockIdx.y * 128;
    const int n0 = blockIdx.x * 128;
    const __nv_bfloat16* Xb = g_xb + (size_t)b * CDIM * NPix;
    __nv_bfloat16*       Cb = g_qkv + (size_t)b * O3 * NPix;

    const int tid  = threadIdx.x;
    const int lane = tid & 31;
    const int wid  = tid >> 5;
    const int wm0  = (wid & 3) * 32;
    const int wn0  = (wid >> 2) * 64;

    float acc[2][8][4] = {};

    for (int c0 = 0; c0 < CDIM; c0 += 32) {
        {   // A tile: 128 x 32
            int row = tid >> 1, colg = (tid & 1) * 16;
            const uint4* src = (const uint4*)&g_wq[(size_t)(o0 + row) * CDIM + c0 + colg];
            *(uint4*)&As[row][colg]     = src[0];
            *(uint4*)&As[row][colg + 8] = src[1];
        }
        {   // B tile: 32 x 128
            int row = tid >> 3, colg = (tid & 7) * 16;
            const uint4* src = (const uint4*)&Xb[(size_t)(c0 + row) * NPix + n0 + colg];
            *(uint4*)&Bs[row][colg]     = src[0];
            *(uint4*)&Bs[row][colg + 8] = src[1];
        }
        __syncthreads();

        #pragma unroll
        for (int kk = 0; kk < 32; kk += 16) {
            uint32_t a[2][4];
            #pragma unroll
            for (int mi = 0; mi < 2; mi++) {
                uint32_t ad = cvta_s(&As[wm0 + mi * 16 + (lane & 15)][kk + (lane >> 4) * 8]);
                LDSM_X4(a[mi][0], a[mi][1], a[mi][2], a[mi][3], ad);
            }
            uint32_t bf[8][2];
            #pragma unroll
            for (int np = 0; np < 4; np++) {
                uint32_t ad = cvta_s(&Bs[kk + ((lane >> 3) & 1) * 8 + (lane & 7)]
                                        [wn0 + np * 16 + (lane >> 4) * 8]);
                uint32_t r0, r1, r2, r3;
                LDSM_X4_T(r0, r1, r2, r3, ad);
                bf[2*np][0] = r0; bf[2*np][1] = r1;
                bf[2*np+1][0] = r2; bf[2*np+1][1] = r3;
            }
            #pragma unroll
            for (int mi = 0; mi < 2; mi++)
                #pragma unroll
                for (int ni = 0; ni < 8; ni++)
                    MMA_BF16(acc[mi][ni], a[mi], bf[ni][0], bf[ni][1]);
        }
        __syncthreads();
    }

    #pragma unroll
    for (int mi = 0; mi < 2; mi++) {
        int r0 = o0 + wm0 + mi * 16 + (lane >> 2);
        #pragma unroll
        for (int ni = 0; ni < 8; ni++) {
            int cc = n0 + wn0 + ni * 8 + (lane & 3) * 2;
            __nv_bfloat162 v0, v1;
            v0.x = __float2bfloat16_rn(acc[mi][ni][0]);
            v0.y = __float2bfloat16_rn(acc[mi][ni][1]);
            v1.x = __float2bfloat16_rn(acc[mi][ni][2]);
            v1.y = __float2bfloat16_rn(acc[mi][ni][3]);
            *(__nv_bfloat162*)&Cb[(size_t)r0 * NPix + cc]       = v0;
            *(__nv_bfloat162*)&Cb[(size_t)(r0 + 8) * NPix + cc] = v1;
        }
    }
}

// ---------------------------------------------------------------------------
// Kernel 2: softmax over n of the K rows (rows [256,512) per batch), in-place bf16
// ---------------------------------------------------------------------------
__global__ __launch_bounds__(256) void k_softmax() {
    const int r  = blockIdx.x;
    const int b  = r >> 8;
    const int hr = r & 255;
    __nv_bfloat162* p = (__nv_bfloat162*)(g_qkv + (size_t)b * O3 * NPix
                                          + (size_t)(CDIM + hr) * NPix);
    __shared__ float buf[NPix];
    __shared__ float red[256];
    const int tid = threadIdx.x;

    float m = -1e30f;
    for (int i = tid; i < NPix / 2; i += 256) {
        __nv_bfloat162 v = p[i];
        float f0 = __bfloat162float(v.x), f1 = __bfloat162float(v.y);
        buf[2*i] = f0; buf[2*i+1] = f1;
        m = fmaxf(m, fmaxf(f0, f1));
    }
    red[tid] = m; __syncthreads();
    for (int s = 128; s > 0; s >>= 1) {
        if (tid < s) red[tid] = fmaxf(red[tid], red[tid + s]);
        __syncthreads();
    }
    m = red[0]; __syncthreads();

    float sum = 0.f;
    for (int i = tid; i < NPix; i += 256) sum += __expf(buf[i] - m);
    red[tid] = sum; __syncthreads();
    for (int s = 128; s > 0; s >>= 1) {
        if (tid < s) red[tid] += red[tid + s];
        __syncthreads();
    }
    const float inv = 1.0f / red[0];

    for (int i = tid; i < NPix / 2; i += 256) {
        __nv_bfloat162 v;
        v.x = __float2bfloat16_rn(__expf(buf[2*i]   - m) * inv);
        v.y = __float2bfloat16_rn(__expf(buf[2*i+1] - m) * inv);
        p[i] = v;
    }
}

// ---------------------------------------------------------------------------
// Kernel 3: partial context ctxp[s][bh][d][e] = sum_{n in split} k[d,n]*v[e,n]
// bf16 HMMA. grid (NSPLIT, 64), 256 threads.
// ---------------------------------------------------------------------------
__global__ __launch_bounds__(256) void k_ctx() {
    const int split = blockIdx.x;
    const int bh = blockIdx.y;
    const int b = bh >> 2;
    const int h = bh & 3;
    const __nv_bfloat16* kp = g_qkv + (size_t)b * O3 * NPix + (size_t)(CDIM + h * DH) * NPix;
    const __nv_bfloat16* vp = g_qkv + (size_t)b * O3 * NPix + (size_t)(2 * CDIM + h * DH) * NPix;

    __shared__ __nv_bfloat16 Ks[64][40];
    __shared__ __nv_bfloat16 Vs[64][40];

    const int tid  = threadIdx.x;
    const int lane = tid & 31;
    const int wid  = tid >> 5;
    const int wm0  = (wid & 3) * 16;   // d
    const int wn0  = (wid >> 2) * 32;  // e

    float acc[4][4] = {};

    const int nbeg = split * (NPix / NSPLIT);
    const int nend = nbeg + (NPix / NSPLIT);

    for (int n0 = nbeg; n0 < nend; n0 += 32) {
        {
            int row = tid >> 2, colg = (tid & 3) * 8;
            *(uint4*)&Ks[row][colg] = *(const uint4*)&kp[(size_t)row * NPix + n0 + colg];
            *(uint4*)&Vs[row][colg] = *(const uint4*)&vp[(size_t)row * NPix + n0 + colg];
        }
        __syncthreads();

        #pragma unroll
        for (int kk = 0; kk < 32; kk += 16) {
            uint32_t a[4];
            {
                uint32_t ad = cvta_s(&Ks[wm0 + (lane & 15)][kk + (lane >> 4) * 8]);
                LDSM_X4(a[0], a[1], a[2], a[3], ad);
            }
            uint32_t bf[4][2];
            #pragma unroll
            for (int np = 0; np < 2; np++) {
                int g = lane >> 3, rr = lane & 7;
                uint32_t ad = cvta_s(&Vs[wn0 + np * 16 + (g >> 1) * 8 + rr][kk + (g & 1) * 8]);
                uint32_t r0, r1, r2, r3;
                LDSM_X4(r0, r1, r2, r3, ad);
                bf[2*np][0] = r0; bf[2*np][1] = r1;
                bf[2*np+1][0] = r2; bf[2*np+1][1] = r3;
            }
            #pragma unroll
            for (int ni = 0; ni < 4; ni++)
                MMA_BF16(acc[ni], a, bf[ni][0], bf[ni][1]);
        }
        __syncthreads();
    }

    float* cp = g_ctxp + ((size_t)split * (BATCH * HEADS) + bh) * (DH * DH);
    #pragma unroll
    for (int ni = 0; ni < 4; ni++) {
        int d = wm0 + (lane >> 2);
        int e = wn0 + ni * 8 + (lane & 3) * 2;
        *(float2*)&cp[(size_t)d * DH + e]       = make_float2(acc[ni][0], acc[ni][1]);
        *(float2*)&cp[(size_t)(d + 8) * DH + e] = make_float2(acc[ni][2], acc[ni][3]);
    }
}

// ---------------------------------------------------------------------------
// Kernel 4: M[b][o][h*64+d] = gamma[o] * sum_e w_out[o][h*64+e]*ctx[b,h][d][e]
// grid (64 bh, 4 og), 256 threads. Output bf16 into g_M.
// ---------------------------------------------------------------------------
__global__ __launch_bounds__(256) void k_mix(const float* __restrict__ Wout,
                                             const float* __restrict__ gamma) {
    const int bh = blockIdx.x;
    const int og = blockIdx.y;
    const int b = bh >> 2;
    const int h = bh & 3;

    __shared__ float cs[64][65];
    const int tid = threadIdx.x;

    for (int idx = tid; idx < DH * DH; idx += 256) {
        float s = 0.f;
        #pragma unroll
        for (int sp = 0; sp < NSPLIT; sp++)
            s += g_ctxp[((size_t)sp * (BATCH * HEADS) + bh) * (DH * DH) + idx];
        cs[idx >> 6][idx & 63] = s;
    }
    __syncthreads();

    const int o  = og * 64 + (tid >> 2);
    const int d0 = (tid & 3) * 16;

    float acc[16];
    #pragma unroll
    for (int j = 0; j < 16; j++) acc[j] = 0.f;

    for (int e = 0; e < 64; e++) {
        const float w = Wout[(size_t)o * CDIM + h * DH + e];
        #pragma unroll
        for (int j = 0; j < 16; j++)
            acc[j] = fmaf(w, cs[d0 + j][e], acc[j]);
    }
    const float g = gamma[o];
    __nv_bfloat16* mp = g_M + ((size_t)b * CDIM + o) * CDIM + h * DH + d0;
    #pragma unroll
    for (int j = 0; j < 16; j++) mp[j] = __float2bfloat16_rn(g * acc[j]);
}

// ---------------------------------------------------------------------------
// Kernel 5: y[b,o,n] = sum_c M[b][o][c]*q[b,c,n] + gamma[o]*b_out[o] + x[b,o,n]
// bf16 HMMA with fused fp32 epilogue.
// ---------------------------------------------------------------------------
__global__ __launch_bounds__(256) void k_out(const float* __restrict__ X,
                                             const float* __restrict__ b_out,
                                             const float* __restrict__ gamma,
                                             float* __restrict__ Y) {
    __shared__ __nv_bfloat16 As[128][40];
    __shared__ __nv_bfloat16 Bs[32][136];

    const int b  = blockIdx.z;
    const int o0 = blockIdx.y * 128;
    const int n0 = blockIdx.x * 128;
    const __nv_bfloat16* Mb = g_M + (size_t)b * CDIM * CDIM;
    const __nv_bfloat16* Qb = g_qkv + (size_t)b * O3 * NPix;
    const float* Xb = X + (size_t)b * CDIM * NPix;
    float*       Yb = Y + (size_t)b * CDIM * NPix;

    const int tid  = threadIdx.x;
    const int lane = tid & 31;
    const int wid  = tid >> 5;
    const int wm0  = (wid & 3) * 32;
    const int wn0  = (wid >> 2) * 64;

    float acc[2][8][4] = {};

    for (int c0 = 0; c0 < CDIM; c0 += 32) {
        {
            int row = tid >> 1, colg = (tid & 1) * 16;
            const uint4* src = (const uint4*)&Mb[(size_t)(o0 + row) * CDIM + c0 + colg];
            *(uint4*)&As[row][colg]     = src[0];
            *(uint4*)&As[row][colg + 8] = src[1];
        }
        {
            int row = tid >> 3, colg = (tid & 7) * 16;
            const uint4* src = (const uint4*)&Qb[(size_t)(c0 + row) * NPix + n0 + colg];
            *(uint4*)&Bs[row][colg]     = src[0];
            *(uint4*)&Bs[row][colg + 8] = src[1];
        }
        __syncthreads();

        #pragma unroll
        for (int kk = 0; kk < 32; kk += 16) {
            uint32_t a[2][4];
            #pragma unroll
            for (int mi = 0; mi < 2; mi++) {
                uint32_t ad = cvta_s(&As[wm0 + mi * 16 + (lane & 15)][kk + (lane >> 4) * 8]);
                LDSM_X4(a[mi][0], a[mi][1], a[mi][2], a[mi][3], ad);
            }
            uint32_t bf[8][2];
            #pragma unroll
            for (int np = 0; np < 4; np++) {
                uint32_t ad = cvta_s(&Bs[kk + ((lane >> 3) & 1) * 8 + (lane & 7)]
                                        [wn0 + np * 16 + (lane >> 4) * 8]);
                uint32_t r0, r1, r2, r3;
                LDSM_X4_T(r0, r1, r2, r3, ad);
                bf[2*np][0] = r0; bf[2*np][1] = r1;
                bf[2*np+1][0] = r2; bf[2*np+1][1] = r3;
            }
            #pragma unroll
            for (int mi = 0; mi < 2; mi++)
                #pragma unroll
                for (int ni = 0; ni < 8; ni++)
                    MMA_BF16(acc[mi][ni], a[mi], bf[ni][0], bf[ni][1]);
        }
        __syncthreads();
    }

    #pragma unroll
    for (int mi = 0; mi < 2; mi++) {
        int r0 = o0 + wm0 + mi * 16 + (lane >> 2);
        int r1 = r0 + 8;
        float bias0 = gamma[r0] * b_out[r0];
        float bias1 = gamma[r1] * b_out[r1];
        #pragma unroll
        for (int ni = 0; ni < 8; ni++) {
            int cc = n0 + wn0 + ni * 8 + (lane & 3) * 2;
            size_t off0 = (size_t)r0 * NPix + cc;
            size_t off1 = (size_t)r1 * NPix + cc;
            float2 x0 = *(const float2*)&Xb[off0];
            float2 x1 = *(const float2*)&Xb[off1];
            float2 y0 = make_float2(acc[mi][ni][0] + bias0 + x0.x,
                                    acc[mi][ni][1] + bias0 + x0.y);
            float2 y1 = make_float2(acc[mi][ni][2] + bias1 + x1.x,
                                    acc[mi][ni][3] + bias1 + x1.y);
            *(float2*)&Yb[off0] = y0;
            *(float2*)&Yb[off1] = y1;
        }
    }
}

// ---------------------------------------------------------------------------
extern "C" void kernel_launch(void* const* d_in, const int* in_sizes, int n_in,
                              void* d_out, int out_size) {
    const float* x      = (const float*)d_in[0];
    const float* w_qkv  = (const float*)d_in[1];
    const float* w_out  = (const float*)d_in[2];
    const float* b_out  = (const float*)d_in[3];
    const float* gamma  = (const float*)d_in[4];
    float* y = (float*)d_out;

    k_cvt_x<<<(BATCH * CDIM * NPix) / 1024, 256>>>(x);
    k_cvt_w<<<(O3 * CDIM) / 1024, 256>>>(w_qkv);
    k_qkv<<<dim3(NPix / 128, O3 / 128, BATCH), 256>>>();
    k_softmax<<<BATCH * HEADS * DH, 256>>>();
    k_ctx<<<dim3(NSPLIT, BATCH * HEADS), 256>>>();
    k_mix<<<dim3(BATCH * HEADS, 4), 256>>>(w_out, gamma);
    k_out<<<dim3(NPix / 128, CDIM / 128, BATCH), 256>>>(x, b_out, gamma, y);
}

// round 6
// speedup vs baseline: 5.0984x; 1.3518x over previous
#include <cuda_runtime.h>
#include <cuda_bf16.h>
#include <cstdint>

// Problem constants
#define BATCH 16
#define CDIM  256
#define NPix  4096
#define HEADS 4
#define DH    64
#define O3    768
#define NSPLIT 8

// Scratch (__device__ globals: allocation-free rule)
__device__ __nv_bfloat16 g_qkv[(size_t)BATCH * O3 * NPix];     // 100 MB
__device__ __nv_bfloat16 g_xb [(size_t)BATCH * CDIM * NPix];   // 33 MB
__device__ __nv_bfloat16 g_wq [(size_t)O3 * CDIM];             // 384 KB
__device__ float g_ctxp[(size_t)NSPLIT * BATCH * HEADS * DH * DH]; // 8 MB
__device__ float g_zp  [(size_t)NSPLIT * BATCH * HEADS * DH];      // 128 KB
__device__ __nv_bfloat16 g_M[(size_t)BATCH * CDIM * CDIM];     // 2 MB

__device__ __forceinline__ uint32_t cvta_s(const void* p) {
    return (uint32_t)__cvta_generic_to_shared(p);
}
__device__ __forceinline__ void cp16(uint32_t dst, const void* src) {
    asm volatile("cp.async.cg.shared.global [%0], [%1], 16;" :: "r"(dst), "l"(src));
}
#define CP_COMMIT() asm volatile("cp.async.commit_group;")
#define CP_WAIT(n)  asm volatile("cp.async.wait_group %0;" :: "n"(n))

#define LDSM_X4(r0,r1,r2,r3,addr) \
    asm volatile("ldmatrix.sync.aligned.m8n8.x4.shared.b16 {%0,%1,%2,%3}, [%4];" \
                 : "=r"(r0),"=r"(r1),"=r"(r2),"=r"(r3) : "r"(addr))
#define LDSM_X4_T(r0,r1,r2,r3,addr) \
    asm volatile("ldmatrix.sync.aligned.m8n8.x4.trans.shared.b16 {%0,%1,%2,%3}, [%4];" \
                 : "=r"(r0),"=r"(r1),"=r"(r2),"=r"(r3) : "r"(addr))
#define MMA_BF16(c,a,b0,b1) \
    asm volatile("mma.sync.aligned.m16n8k16.row.col.f32.bf16.bf16.f32 " \
                 "{%0,%1,%2,%3},{%4,%5,%6,%7},{%8,%9},{%0,%1,%2,%3};" \
                 : "+f"((c)[0]),"+f"((c)[1]),"+f"((c)[2]),"+f"((c)[3]) \
                 : "r"((a)[0]),"r"((a)[1]),"r"((a)[2]),"r"((a)[3]),"r"(b0),"r"(b1))

// ---------------------------------------------------------------------------
// Conversion kernels (fp32 -> bf16)
// ---------------------------------------------------------------------------
__global__ __launch_bounds__(256) void k_cvt_x(const float* __restrict__ x) {
    size_t i = ((size_t)blockIdx.x * 256 + threadIdx.x) * 4;
    float4 v = *(const float4*)&x[i];
    __nv_bfloat162 lo, hi;
    lo.x = __float2bfloat16_rn(v.x); lo.y = __float2bfloat16_rn(v.y);
    hi.x = __float2bfloat16_rn(v.z); hi.y = __float2bfloat16_rn(v.w);
    *(__nv_bfloat162*)&g_xb[i]     = lo;
    *(__nv_bfloat162*)&g_xb[i + 2] = hi;
}
__global__ __launch_bounds__(256) void k_cvt_w(const float* __restrict__ w) {
    size_t i = ((size_t)blockIdx.x * 256 + threadIdx.x) * 4;
    float4 v = *(const float4*)&w[i];
    __nv_bfloat162 lo, hi;
    lo.x = __float2bfloat16_rn(v.x); lo.y = __float2bfloat16_rn(v.y);
    hi.x = __float2bfloat16_rn(v.z); hi.y = __float2bfloat16_rn(v.w);
    *(__nv_bfloat162*)&g_wq[i]     = lo;
    *(__nv_bfloat162*)&g_wq[i + 2] = hi;
}

// ---------------------------------------------------------------------------
// Kernel 1: qkv[b,o,n] = sum_c W[o,c]*x[b,c,n]
// bf16 HMMA, 128x128x32 tiles, cp.async double-buffered
// ---------------------------------------------------------------------------
__global__ __launch_bounds__(256, 2) void k_qkv() {
    __shared__ __nv_bfloat16 As[2][128][40];    // [o][c]
    __shared__ __nv_bfloat16 Bs[2][32][136];    // [c][n]

    const int b  = blockIdx.z;
    const int o0 = blockIdx.y * 128;
    const int n0 = blockIdx.x * 128;
    const __nv_bfloat16* Xb = g_xb + (size_t)b * CDIM * NPix;
    __nv_bfloat16*       Cb = g_qkv + (size_t)b * O3 * NPix;

    const int tid  = threadIdx.x;
    const int lane = tid & 31;
    const int wid  = tid >> 5;
    const int wm0  = (wid & 3) * 32;
    const int wn0  = (wid >> 2) * 64;

    // Precomputed staging coordinates (2 chunks per operand per thread)
    const int aR0 = tid >> 2,          aC0 = (tid & 3) * 8;
    const int aR1 = (tid + 256) >> 2,  aC1 = ((tid + 256) & 3) * 8;
    const int bR0 = tid >> 4,          bC0 = (tid & 15) * 8;
    const int bR1 = (tid + 256) >> 4,  bC1 = ((tid + 256) & 15) * 8;
    const __nv_bfloat16* aS0 = &g_wq[(size_t)(o0 + aR0) * CDIM + aC0];
    const __nv_bfloat16* aS1 = &g_wq[(size_t)(o0 + aR1) * CDIM + aC1];
    const __nv_bfloat16* bS0 = &Xb[(size_t)bR0 * NPix + n0 + bC0];
    const __nv_bfloat16* bS1 = &Xb[(size_t)bR1 * NPix + n0 + bC1];

    auto stage = [&](int buf, int c0) {
        cp16(cvta_s(&As[buf][aR0][aC0]), aS0 + c0);
        cp16(cvta_s(&As[buf][aR1][aC1]), aS1 + c0);
        cp16(cvta_s(&Bs[buf][bR0][bC0]), bS0 + (size_t)c0 * NPix);
        cp16(cvta_s(&Bs[buf][bR1][bC1]), bS1 + (size_t)c0 * NPix);
    };

    float acc[2][8][4] = {};

    stage(0, 0);
    CP_COMMIT();

    #pragma unroll
    for (int it = 0; it < 8; it++) {          // CDIM/32 = 8 k-steps
        const int buf = it & 1;
        if (it < 7) { stage(buf ^ 1, (it + 1) * 32); CP_COMMIT(); }
        if (it < 7) { CP_WAIT(1); } else { CP_WAIT(0); }
        __syncthreads();

        #pragma unroll
        for (int kk = 0; kk < 32; kk += 16) {
            uint32_t a[2][4];
            #pragma unroll
            for (int mi = 0; mi < 2; mi++) {
                uint32_t ad = cvta_s(&As[buf][wm0 + mi * 16 + (lane & 15)][kk + (lane >> 4) * 8]);
                LDSM_X4(a[mi][0], a[mi][1], a[mi][2], a[mi][3], ad);
            }
            uint32_t bfr[8][2];
            #pragma unroll
            for (int np = 0; np < 4; np++) {
                uint32_t ad = cvta_s(&Bs[buf][kk + ((lane >> 3) & 1) * 8 + (lane & 7)]
                                            [wn0 + np * 16 + (lane >> 4) * 8]);
                uint32_t r0, r1, r2, r3;
                LDSM_X4_T(r0, r1, r2, r3, ad);
                bfr[2*np][0] = r0; bfr[2*np][1] = r1;
                bfr[2*np+1][0] = r2; bfr[2*np+1][1] = r3;
            }
            #pragma unroll
            for (int mi = 0; mi < 2; mi++)
                #pragma unroll
                for (int ni = 0; ni < 8; ni++)
                    MMA_BF16(acc[mi][ni], a[mi], bfr[ni][0], bfr[ni][1]);
        }
        __syncthreads();
    }

    #pragma unroll
    for (int mi = 0; mi < 2; mi++) {
        int r0 = o0 + wm0 + mi * 16 + (lane >> 2);
        #pragma unroll
        for (int ni = 0; ni < 8; ni++) {
            int cc = n0 + wn0 + ni * 8 + (lane & 3) * 2;
            __nv_bfloat162 v0, v1;
            v0.x = __float2bfloat16_rn(acc[mi][ni][0]);
            v0.y = __float2bfloat16_rn(acc[mi][ni][1]);
            v1.x = __float2bfloat16_rn(acc[mi][ni][2]);
            v1.y = __float2bfloat16_rn(acc[mi][ni][3]);
            *(__nv_bfloat162*)&Cb[(size_t)r0 * NPix + cc]       = v0;
            *(__nv_bfloat162*)&Cb[(size_t)(r0 + 8) * NPix + cc] = v1;
        }
    }
}

// ---------------------------------------------------------------------------
// Kernel 2: partial UNNORMALIZED context + partial Z.
//   ctxp[s][bh][d][e] = sum_{n in split} exp(k[d,n]) * v[e,n]
//   zp[s][bh][d]      = sum_{n in split} exp(k[d,n])
// Normalization by 1/Z happens in k_mix. No softmax kernel needed.
// ---------------------------------------------------------------------------
__global__ __launch_bounds__(256) void k_ctx() {
    const int split = blockIdx.x;
    const int bh = blockIdx.y;
    const int b = bh >> 2;
    const int h = bh & 3;
    const __nv_bfloat16* kp = g_qkv + (size_t)b * O3 * NPix + (size_t)(CDIM + h * DH) * NPix;
    const __nv_bfloat16* vp = g_qkv + (size_t)b * O3 * NPix + (size_t)(2 * CDIM + h * DH) * NPix;

    __shared__ __nv_bfloat16 Ks[64][40];
    __shared__ __nv_bfloat16 Vs[64][40];

    const int tid  = threadIdx.x;
    const int lane = tid & 31;
    const int wid  = tid >> 5;
    const int wm0  = (wid & 3) * 16;   // d
    const int wn0  = (wid >> 2) * 32;  // e

    const int srow  = tid >> 2;        // staging row (d or e), 0..63
    const int scolg = (tid & 3) * 8;   // staging col group

    float acc[4][4] = {};
    float zacc = 0.f;

    const int nbeg = split * (NPix / NSPLIT);
    const int nend = nbeg + (NPix / NSPLIT);

    for (int n0 = nbeg; n0 < nend; n0 += 32) {
        {   // K: load 8 bf16, exponentiate, accumulate partial Z, store bf16
            const __nv_bfloat162* src =
                (const __nv_bfloat162*)&kp[(size_t)srow * NPix + n0 + scolg];
            __nv_bfloat162 outp[4];
            #pragma unroll
            for (int j = 0; j < 4; j++) {
                float2 f = __bfloat1622float2(src[j]);
                float e0 = __expf(f.x);
                float e1 = __expf(f.y);
                zacc += e0 + e1;
                outp[j].x = __float2bfloat16_rn(e0);
                outp[j].y = __float2bfloat16_rn(e1);
            }
            *(uint4*)&Ks[srow][scolg] = *(uint4*)outp;
            // V: straight copy
            *(uint4*)&Vs[srow][scolg] = *(const uint4*)&vp[(size_t)srow * NPix + n0 + scolg];
        }
        __syncthreads();

        #pragma unroll
        for (int kk = 0; kk < 32; kk += 16) {
            uint32_t a[4];
            {
                uint32_t ad = cvta_s(&Ks[wm0 + (lane & 15)][kk + (lane >> 4) * 8]);
                LDSM_X4(a[0], a[1], a[2], a[3], ad);
            }
            uint32_t bfr[4][2];
            #pragma unroll
            for (int np = 0; np < 2; np++) {
                int g = lane >> 3, rr = lane & 7;
                uint32_t ad = cvta_s(&Vs[wn0 + np * 16 + (g >> 1) * 8 + rr][kk + (g & 1) * 8]);
                uint32_t r0, r1, r2, r3;
                LDSM_X4(r0, r1, r2, r3, ad);
                bfr[2*np][0] = r0; bfr[2*np][1] = r1;
                bfr[2*np+1][0] = r2; bfr[2*np+1][1] = r3;
            }
            #pragma unroll
            for (int ni = 0; ni < 4; ni++)
                MMA_BF16(acc[ni], a, bfr[ni][0], bfr[ni][1]);
        }
        __syncthreads();
    }

    // Reduce partial Z across the 4 staging threads of each row (same warp)
    zacc += __shfl_xor_sync(0xffffffffu, zacc, 1);
    zacc += __shfl_xor_sync(0xffffffffu, zacc, 2);
    if ((tid & 3) == 0)
        g_zp[((size_t)split * (BATCH * HEADS) + bh) * DH + srow] = zacc;

    float* cp = g_ctxp + ((size_t)split * (BATCH * HEADS) + bh) * (DH * DH);
    #pragma unroll
    for (int ni = 0; ni < 4; ni++) {
        int d = wm0 + (lane >> 2);
        int e = wn0 + ni * 8 + (lane & 3) * 2;
        *(float2*)&cp[(size_t)d * DH + e]       = make_float2(acc[ni][0], acc[ni][1]);
        *(float2*)&cp[(size_t)(d + 8) * DH + e] = make_float2(acc[ni][2], acc[ni][3]);
    }
}

// ---------------------------------------------------------------------------
// Kernel 3: M[b][o][h*64+d] = gamma[o]/Z_d * sum_e w_out[o][h*64+e]*ctx[b,h][d][e]
// ---------------------------------------------------------------------------
__global__ __launch_bounds__(256) void k_mix(const float* __restrict__ Wout,
                                             const float* __restrict__ gamma) {
    const int bh = blockIdx.x;
    const int og = blockIdx.y;
    const int b = bh >> 2;
    const int h = bh & 3;

    __shared__ float cs[64][65];
    __shared__ float zs[64];
    const int tid = threadIdx.x;

    if (tid < 64) {
        float s = 0.f;
        #pragma unroll
        for (int sp = 0; sp < NSPLIT; sp++)
            s += g_zp[((size_t)sp * (BATCH * HEADS) + bh) * DH + tid];
        zs[tid] = 1.0f / s;
    }
    __syncthreads();

    for (int idx = tid; idx < DH * DH; idx += 256) {
        float s = 0.f;
        #pragma unroll
        for (int sp = 0; sp < NSPLIT; sp++)
            s += g_ctxp[((size_t)sp * (BATCH * HEADS) + bh) * (DH * DH) + idx];
        cs[idx >> 6][idx & 63] = s * zs[idx >> 6];
    }
    __syncthreads();

    const int o  = og * 64 + (tid >> 2);
    const int d0 = (tid & 3) * 16;

    float acc[16];
    #pragma unroll
    for (int j = 0; j < 16; j++) acc[j] = 0.f;

    for (int e = 0; e < 64; e++) {
        const float w = Wout[(size_t)o * CDIM + h * DH + e];
        #pragma unroll
        for (int j = 0; j < 16; j++)
            acc[j] = fmaf(w, cs[d0 + j][e], acc[j]);
    }
    const float g = gamma[o];
    __nv_bfloat16* mp = g_M + ((size_t)b * CDIM + o) * CDIM + h * DH + d0;
    #pragma unroll
    for (int j = 0; j < 16; j++) mp[j] = __float2bfloat16_rn(g * acc[j]);
}

// ---------------------------------------------------------------------------
// Kernel 4: y[b,o,n] = sum_c M[b][o][c]*q[b,c,n] + gamma[o]*b_out[o] + x[b,o,n]
// bf16 HMMA, cp.async double-buffered, fused fp32 epilogue
// ---------------------------------------------------------------------------
__global__ __launch_bounds__(256, 2) void k_out(const float* __restrict__ X,
                                                const float* __restrict__ b_out,
                                                const float* __restrict__ gamma,
                                                float* __restrict__ Y) {
    __shared__ __nv_bfloat16 As[2][128][40];
    __shared__ __nv_bfloat16 Bs[2][32][136];

    const int b  = blockIdx.z;
    const int o0 = blockIdx.y * 128;
    const int n0 = blockIdx.x * 128;
    const __nv_bfloat16* Mb = g_M + (size_t)b * CDIM * CDIM;
    const __nv_bfloat16* Qb = g_qkv + (size_t)b * O3 * NPix;
    const float* Xb = X + (size_t)b * CDIM * NPix;
    float*       Yb = Y + (size_t)b * CDIM * NPix;

    const int tid  = threadIdx.x;
    const int lane = tid & 31;
    const int wid  = tid >> 5;
    const int wm0  = (wid & 3) * 32;
    const int wn0  = (wid >> 2) * 64;

    const int aR0 = tid >> 2,          aC0 = (tid & 3) * 8;
    const int aR1 = (tid + 256) >> 2,  aC1 = ((tid + 256) & 3) * 8;
    const int bR0 = tid >> 4,          bC0 = (tid & 15) * 8;
    const int bR1 = (tid + 256) >> 4,  bC1 = ((tid + 256) & 15) * 8;
    const __nv_bfloat16* aS0 = &Mb[(size_t)(o0 + aR0) * CDIM + aC0];
    const __nv_bfloat16* aS1 = &Mb[(size_t)(o0 + aR1) * CDIM + aC1];
    const __nv_bfloat16* bS0 = &Qb[(size_t)bR0 * NPix + n0 + bC0];
    const __nv_bfloat16* bS1 = &Qb[(size_t)bR1 * NPix + n0 + bC1];

    auto stage = [&](int buf, int c0) {
        cp16(cvta_s(&As[buf][aR0][aC0]), aS0 + c0);
        cp16(cvta_s(&As[buf][aR1][aC1]), aS1 + c0);
        cp16(cvta_s(&Bs[buf][bR0][bC0]), bS0 + (size_t)c0 * NPix);
        cp16(cvta_s(&Bs[buf][bR1][bC1]), bS1 + (size_t)c0 * NPix);
    };

    float acc[2][8][4] = {};

    stage(0, 0);
    CP_COMMIT();

    #pragma unroll
    for (int it = 0; it < 8; it++) {
        const int buf = it & 1;
        if (it < 7) { stage(buf ^ 1, (it + 1) * 32); CP_COMMIT(); }
        if (it < 7) { CP_WAIT(1); } else { CP_WAIT(0); }
        __syncthreads();

        #pragma unroll
        for (int kk = 0; kk < 32; kk += 16) {
            uint32_t a[2][4];
            #pragma unroll
            for (int mi = 0; mi < 2; mi++) {
                uint32_t ad = cvta_s(&As[buf][wm0 + mi * 16 + (lane & 15)][kk + (lane >> 4) * 8]);
                LDSM_X4(a[mi][0], a[mi][1], a[mi][2], a[mi][3], ad);
            }
            uint32_t bfr[8][2];
            #pragma unroll
            for (int np = 0; np < 4; np++) {
                uint32_t ad = cvta_s(&Bs[buf][kk + ((lane >> 3) & 1) * 8 + (lane & 7)]
                                            [wn0 + np * 16 + (lane >> 4) * 8]);
                uint32_t r0, r1, r2, r3;
                LDSM_X4_T(r0, r1, r2, r3, ad);
                bfr[2*np][0] = r0; bfr[2*np][1] = r1;
                bfr[2*np+1][0] = r2; bfr[2*np+1][1] = r3;
            }
            #pragma unroll
            for (int mi = 0; mi < 2; mi++)
                #pragma unroll
                for (int ni = 0; ni < 8; ni++)
                    MMA_BF16(acc[mi][ni], a[mi], bfr[ni][0], bfr[ni][1]);
        }
        __syncthreads();
    }

    #pragma unroll
    for (int mi = 0; mi < 2; mi++) {
        int r0 = o0 + wm0 + mi * 16 + (lane >> 2);
        int r1 = r0 + 8;
        float bias0 = gamma[r0] * b_out[r0];
        float bias1 = gamma[r1] * b_out[r1];
        #pragma unroll
        for (int ni = 0; ni < 8; ni++) {
            int cc = n0 + wn0 + ni * 8 + (lane & 3) * 2;
            size_t off0 = (size_t)r0 * NPix + cc;
            size_t off1 = (size_t)r1 * NPix + cc;
            float2 x0 = *(const float2*)&Xb[off0];
            float2 x1 = *(const float2*)&Xb[off1];
            float2 y0 = make_float2(acc[mi][ni][0] + bias0 + x0.x,
                                    acc[mi][ni][1] + bias0 + x0.y);
            float2 y1 = make_float2(acc[mi][ni][2] + bias1 + x1.x,
                                    acc[mi][ni][3] + bias1 + x1.y);
            *(float2*)&Yb[off0] = y0;
            *(float2*)&Yb[off1] = y1;
        }
    }
}

// ---------------------------------------------------------------------------
extern "C" void kernel_launch(void* const* d_in, const int* in_sizes, int n_in,
                              void* d_out, int out_size) {
    const float* x      = (const float*)d_in[0];
    const float* w_qkv  = (const float*)d_in[1];
    const float* w_out  = (const float*)d_in[2];
    const float* b_out  = (const float*)d_in[3];
    const float* gamma  = (const float*)d_in[4];
    float* y = (float*)d_out;

    k_cvt_x<<<(BATCH * CDIM * NPix) / 1024, 256>>>(x);
    k_cvt_w<<<(O3 * CDIM) / 1024, 256>>>(w_qkv);
    k_qkv<<<dim3(NPix / 128, O3 / 128, BATCH), 256>>>();
    k_ctx<<<dim3(NSPLIT, BATCH * HEADS), 256>>>();
    k_mix<<<dim3(BATCH * HEADS, 4), 256>>>(w_out, gamma);
    k_out<<<dim3(NPix / 128, CDIM / 128, BATCH), 256>>>(x, b_out, gamma, y);
}

// round 10
// speedup vs baseline: 5.7108x; 1.1201x over previous
#include <cuda_runtime.h>
#include <cuda_bf16.h>
#include <cstdint>

// Problem constants
#define BATCH 16
#define CDIM  256
#define NPix  4096
#define HEADS 4
#define DH    64
#define O3    768
#define NSPLIT 8

// Scratch (__device__ globals: allocation-free rule)
__device__ __nv_bfloat16 g_qkv[(size_t)BATCH * O3 * NPix];     // K,V live in rows [256,768)
__device__ __nv_bfloat16 g_xb [(size_t)BATCH * CDIM * NPix];   // 33 MB
__device__ __nv_bfloat16 g_wq [(size_t)O3 * CDIM];             // 384 KB
__device__ float g_ctxp[(size_t)NSPLIT * BATCH * HEADS * DH * DH]; // 8 MB
__device__ float g_zp  [(size_t)NSPLIT * BATCH * HEADS * DH];      // 128 KB
__device__ __nv_bfloat16 g_M [(size_t)BATCH * CDIM * CDIM];    // 2 MB
__device__ __nv_bfloat16 g_Mq[(size_t)BATCH * CDIM * CDIM];    // 2 MB  (M @ W_q)

__device__ __forceinline__ uint32_t cvta_s(const void* p) {
    return (uint32_t)__cvta_generic_to_shared(p);
}
__device__ __forceinline__ void cp16(uint32_t dst, const void* src) {
    asm volatile("cp.async.cg.shared.global [%0], [%1], 16;" :: "r"(dst), "l"(src));
}
#define CP_COMMIT() asm volatile("cp.async.commit_group;")
#define CP_WAIT(n)  asm volatile("cp.async.wait_group %0;" :: "n"(n))

#define LDSM_X4(r0,r1,r2,r3,addr) \
    asm volatile("ldmatrix.sync.aligned.m8n8.x4.shared.b16 {%0,%1,%2,%3}, [%4];" \
                 : "=r"(r0),"=r"(r1),"=r"(r2),"=r"(r3) : "r"(addr))
#define LDSM_X4_T(r0,r1,r2,r3,addr) \
    asm volatile("ldmatrix.sync.aligned.m8n8.x4.trans.shared.b16 {%0,%1,%2,%3}, [%4];" \
                 : "=r"(r0),"=r"(r1),"=r"(r2),"=r"(r3) : "r"(addr))
#define MMA_BF16(c,a,b0,b1) \
    asm volatile("mma.sync.aligned.m16n8k16.row.col.f32.bf16.bf16.f32 " \
                 "{%0,%1,%2,%3},{%4,%5,%6,%7},{%8,%9},{%0,%1,%2,%3};" \
                 : "+f"((c)[0]),"+f"((c)[1]),"+f"((c)[2]),"+f"((c)[3]) \
                 : "r"((a)[0]),"r"((a)[1]),"r"((a)[2]),"r"((a)[3]),"r"(b0),"r"(b1))

// ---------------------------------------------------------------------------
// Conversion kernels (fp32 -> bf16)
// ---------------------------------------------------------------------------
__global__ __launch_bounds__(256) void k_cvt_x(const float* __restrict__ x) {
    size_t i = ((size_t)blockIdx.x * 256 + threadIdx.x) * 4;
    float4 v = *(const float4*)&x[i];
    __nv_bfloat162 lo, hi;
    lo.x = __float2bfloat16_rn(v.x); lo.y = __float2bfloat16_rn(v.y);
    hi.x = __float2bfloat16_rn(v.z); hi.y = __float2bfloat16_rn(v.w);
    *(__nv_bfloat162*)&g_xb[i]     = lo;
    *(__nv_bfloat162*)&g_xb[i + 2] = hi;
}
__global__ __launch_bounds__(256) void k_cvt_w(const float* __restrict__ w) {
    size_t i = ((size_t)blockIdx.x * 256 + threadIdx.x) * 4;
    float4 v = *(const float4*)&w[i];
    __nv_bfloat162 lo, hi;
    lo.x = __float2bfloat16_rn(v.x); lo.y = __float2bfloat16_rn(v.y);
    hi.x = __float2bfloat16_rn(v.z); hi.y = __float2bfloat16_rn(v.w);
    *(__nv_bfloat162*)&g_wq[i]     = lo;
    *(__nv_bfloat162*)&g_wq[i + 2] = hi;
}

// ---------------------------------------------------------------------------
// Kernel 1: K,V only. qkv[b,o,n] = sum_c W[o,c]*x[b,c,n], o in [256,768)
// bf16 HMMA, 128x128x32 tiles, cp.async double-buffered
// ---------------------------------------------------------------------------
__global__ __launch_bounds__(256, 2) void k_qkv() {
    __shared__ __nv_bfloat16 As[2][128][40];    // [o][c]
    __shared__ __nv_bfloat16 Bs[2][32][136];    // [c][n]

    const int b  = blockIdx.z;
    const int o0 = CDIM + blockIdx.y * 128;     // skip Q rows
    const int n0 = blockIdx.x * 128;
    const __nv_bfloat16* Xb = g_xb + (size_t)b * CDIM * NPix;
    __nv_bfloat16*       Cb = g_qkv + (size_t)b * O3 * NPix;

    const int tid  = threadIdx.x;
    const int lane = tid & 31;
    const int wid  = tid >> 5;
    const int wm0  = (wid & 3) * 32;
    const int wn0  = (wid >> 2) * 64;

    const int aR0 = tid >> 2,          aC0 = (tid & 3) * 8;
    const int aR1 = (tid + 256) >> 2,  aC1 = ((tid + 256) & 3) * 8;
    const int bR0 = tid >> 4,          bC0 = (tid & 15) * 8;
    const int bR1 = (tid + 256) >> 4,  bC1 = ((tid + 256) & 15) * 8;
    const __nv_bfloat16* aS0 = &g_wq[(size_t)(o0 + aR0) * CDIM + aC0];
    const __nv_bfloat16* aS1 = &g_wq[(size_t)(o0 + aR1) * CDIM + aC1];
    const __nv_bfloat16* bS0 = &Xb[(size_t)bR0 * NPix + n0 + bC0];
    const __nv_bfloat16* bS1 = &Xb[(size_t)bR1 * NPix + n0 + bC1];

    auto stage = [&](int buf, int c0) {
        cp16(cvta_s(&As[buf][aR0][aC0]), aS0 + c0);
        cp16(cvta_s(&As[buf][aR1][aC1]), aS1 + c0);
        cp16(cvta_s(&Bs[buf][bR0][bC0]), bS0 + (size_t)c0 * NPix);
        cp16(cvta_s(&Bs[buf][bR1][bC1]), bS1 + (size_t)c0 * NPix);
    };

    float acc[2][8][4] = {};

    stage(0, 0);
    CP_COMMIT();

    #pragma unroll
    for (int it = 0; it < 8; it++) {          // CDIM/32 = 8 k-steps
        const int buf = it & 1;
        if (it < 7) { stage(buf ^ 1, (it + 1) * 32); CP_COMMIT(); }
        if (it < 7) { CP_WAIT(1); } else { CP_WAIT(0); }
        __syncthreads();

        #pragma unroll
        for (int kk = 0; kk < 32; kk += 16) {
            uint32_t a[2][4];
            #pragma unroll
            for (int mi = 0; mi < 2; mi++) {
                uint32_t ad = cvta_s(&As[buf][wm0 + mi * 16 + (lane & 15)][kk + (lane >> 4) * 8]);
                LDSM_X4(a[mi][0], a[mi][1], a[mi][2], a[mi][3], ad);
            }
            uint32_t bfr[8][2];
            #pragma unroll
            for (int np = 0; np < 4; np++) {
                uint32_t ad = cvta_s(&Bs[buf][kk + ((lane >> 3) & 1) * 8 + (lane & 7)]
                                            [wn0 + np * 16 + (lane >> 4) * 8]);
                uint32_t r0, r1, r2, r3;
                LDSM_X4_T(r0, r1, r2, r3, ad);
                bfr[2*np][0] = r0; bfr[2*np][1] = r1;
                bfr[2*np+1][0] = r2; bfr[2*np+1][1] = r3;
            }
            #pragma unroll
            for (int mi = 0; mi < 2; mi++)
                #pragma unroll
                for (int ni = 0; ni < 8; ni++)
                    MMA_BF16(acc[mi][ni], a[mi], bfr[ni][0], bfr[ni][1]);
        }
        __syncthreads();
    }

    #pragma unroll
    for (int mi = 0; mi < 2; mi++) {
        int r0 = o0 + wm0 + mi * 16 + (lane >> 2);
        #pragma unroll
        for (int ni = 0; ni < 8; ni++) {
            int cc = n0 + wn0 + ni * 8 + (lane & 3) * 2;
            __nv_bfloat162 v0, v1;
            v0.x = __float2bfloat16_rn(acc[mi][ni][0]);
            v0.y = __float2bfloat16_rn(acc[mi][ni][1]);
            v1.x = __float2bfloat16_rn(acc[mi][ni][2]);
            v1.y = __float2bfloat16_rn(acc[mi][ni][3]);
            *(__nv_bfloat162*)&Cb[(size_t)r0 * NPix + cc]       = v0;
            *(__nv_bfloat162*)&Cb[(size_t)(r0 + 8) * NPix + cc] = v1;
        }
    }
}

// ---------------------------------------------------------------------------
// Kernel 2: partial unnormalized context + partial Z.
//   ctxp[s][bh][d][e] = sum_{n in split} exp(k[d,n]) * v[e,n]
//   zp[s][bh][d]      = sum_{n in split} exp(k[d,n])
// 64-wide n-chunks, register LDG prefetch, double-buffered smem, 1 sync/iter.
// ---------------------------------------------------------------------------
__global__ __launch_bounds__(256) void k_ctx() {
    const int split = blockIdx.x;
    const int bh = blockIdx.y;
    const int b = bh >> 2;
    const int h = bh & 3;
    const __nv_bfloat16* kp = g_qkv + (size_t)b * O3 * NPix + (size_t)(CDIM + h * DH) * NPix;
    const __nv_bfloat16* vp = g_qkv + (size_t)b * O3 * NPix + (size_t)(2 * CDIM + h * DH) * NPix;

    __shared__ __nv_bfloat16 Ks[2][64][72];
    __shared__ __nv_bfloat16 Vs[2][64][72];

    const int tid  = threadIdx.x;
    const int lane = tid & 31;
    const int wid  = tid >> 5;
    const int wm0  = (wid & 3) * 16;   // d
    const int wn0  = (wid >> 2) * 32;  // e

    const int srow = tid >> 2;         // staging row, 0..63
    const int scol = (tid & 3) * 16;   // staging col base (16 bf16 per thread)

    const __nv_bfloat16* kSrc = &kp[(size_t)srow * NPix + scol];
    const __nv_bfloat16* vSrc = &vp[(size_t)srow * NPix + scol];

    float acc[4][4] = {};
    float zacc = 0.f;
    const int nbeg = split * (NPix / NSPLIT);

    uint4 kr0, kr1, vr0, vr1;
    kr0 = *(const uint4*)(kSrc + nbeg);     kr1 = *(const uint4*)(kSrc + nbeg + 8);
    vr0 = *(const uint4*)(vSrc + nbeg);     vr1 = *(const uint4*)(vSrc + nbeg + 8);

    #pragma unroll
    for (int it = 0; it < 8; it++) {        // 512/64 = 8 chunks per split
        const int buf = it & 1;
        {   // exp(K) into smem, V straight copy
            __nv_bfloat162 ko[8];
            const __nv_bfloat162* ka = (const __nv_bfloat162*)&kr0;
            const __nv_bfloat162* kb = (const __nv_bfloat162*)&kr1;
            #pragma unroll
            for (int j = 0; j < 4; j++) {
                float2 f = __bfloat1622float2(ka[j]);
                float e0 = __expf(f.x), e1 = __expf(f.y);
                zacc += e0 + e1;
                ko[j].x = __float2bfloat16_rn(e0);
                ko[j].y = __float2bfloat16_rn(e1);
            }
            #pragma unroll
            for (int j = 0; j < 4; j++) {
                float2 f = __bfloat1622float2(kb[j]);
                float e0 = __expf(f.x), e1 = __expf(f.y);
                zacc += e0 + e1;
                ko[4 + j].x = __float2bfloat16_rn(e0);
                ko[4 + j].y = __float2bfloat16_rn(e1);
            }
            *(uint4*)&Ks[buf][srow][scol]     = *(uint4*)&ko[0];
            *(uint4*)&Ks[buf][srow][scol + 8] = *(uint4*)&ko[4];
            *(uint4*)&Vs[buf][srow][scol]     = vr0;
            *(uint4*)&Vs[buf][srow][scol + 8] = vr1;
        }
        __syncthreads();

        if (it < 7) {   // prefetch next chunk; LDG latency hides under MMA
            const int nn = nbeg + (it + 1) * 64;
            kr0 = *(const uint4*)(kSrc + nn);     kr1 = *(const uint4*)(kSrc + nn + 8);
            vr0 = *(const uint4*)(vSrc + nn);     vr1 = *(const uint4*)(vSrc + nn + 8);
        }

        #pragma unroll
        for (int kk = 0; kk < 64; kk += 16) {
            uint32_t a[4];
            {
                uint32_t ad = cvta_s(&Ks[buf][wm0 + (lane & 15)][kk + (lane >> 4) * 8]);
                LDSM_X4(a[0], a[1], a[2], a[3], ad);
            }
            uint32_t bfr[4][2];
            #pragma unroll
            for (int np = 0; np < 2; np++) {
                int g = lane >> 3, rr = lane & 7;
                uint32_t ad = cvta_s(&Vs[buf][wn0 + np * 16 + (g >> 1) * 8 + rr][kk + (g & 1) * 8]);
                uint32_t r0, r1, r2, r3;
                LDSM_X4(r0, r1, r2, r3, ad);
                bfr[2*np][0] = r0; bfr[2*np][1] = r1;
                bfr[2*np+1][0] = r2; bfr[2*np+1][1] = r3;
            }
            #pragma unroll
            for (int ni = 0; ni < 4; ni++)
                MMA_BF16(acc[ni], a, bfr[ni][0], bfr[ni][1]);
        }
        // no trailing sync: next iteration's STS targets the other buffer
    }

    // Reduce partial Z across the 4 staging threads of each row (same warp quad)
    zacc += __shfl_xor_sync(0xffffffffu, zacc, 1);
    zacc += __shfl_xor_sync(0xffffffffu, zacc, 2);
    if ((tid & 3) == 0)
        g_zp[((size_t)split * (BATCH * HEADS) + bh) * DH + srow] = zacc;

    float* cp = g_ctxp + ((size_t)split * (BATCH * HEADS) + bh) * (DH * DH);
    #pragma unroll
    for (int ni = 0; ni < 4; ni++) {
        int d = wm0 + (lane >> 2);
        int e = wn0 + ni * 8 + (lane & 3) * 2;
        *(float2*)&cp[(size_t)d * DH + e]       = make_float2(acc[ni][0], acc[ni][1]);
        *(float2*)&cp[(size_t)(d + 8) * DH + e] = make_float2(acc[ni][2], acc[ni][3]);
    }
}

// ---------------------------------------------------------------------------
// Kernel 3: M[b][o][h*64+d] = gamma[o]/Z_d * sum_e w_out[o][h*64+e]*ctx[b,h][d][e]
// ---------------------------------------------------------------------------
__global__ __launch_bounds__(256) void k_mix(const float* __restrict__ Wout,
                                             const float* __restrict__ gamma) {
    const int bh = blockIdx.x;
    const int og = blockIdx.y;
    const int b = bh >> 2;
    const int h = bh & 3;

    __shared__ float cs[64][65];
    __shared__ float zs[64];
    const int tid = threadIdx.x;

    if (tid < 64) {
        float s = 0.f;
        #pragma unroll
        for (int sp = 0; sp < NSPLIT; sp++)
            s += g_zp[((size_t)sp * (BATCH * HEADS) + bh) * DH + tid];
        zs[tid] = 1.0f / s;
    }
    __syncthreads();

    for (int idx = tid; idx < DH * DH; idx += 256) {
        float s = 0.f;
        #pragma unroll
        for (int sp = 0; sp < NSPLIT; sp++)
            s += g_ctxp[((size_t)sp * (BATCH * HEADS) + bh) * (DH * DH) + idx];
        cs[idx >> 6][idx & 63] = s * zs[idx >> 6];
    }
    __syncthreads();

    const int o  = og * 64 + (tid >> 2);
    const int d0 = (tid & 3) * 16;

    float acc[16];
    #pragma unroll
    for (int j = 0; j < 16; j++) acc[j] = 0.f;

    for (int e = 0; e < 64; e++) {
        const float w = Wout[(size_t)o * CDIM + h * DH + e];
        #pragma unroll
        for (int j = 0; j < 16; j++)
            acc[j] = fmaf(w, cs[d0 + j][e], acc[j]);
    }
    const float g = gamma[o];
    __nv_bfloat16* mp = g_M + ((size_t)b * CDIM + o) * CDIM + h * DH + d0;
    #pragma unroll
    for (int j = 0; j < 16; j++) mp[j] = __float2bfloat16_rn(g * acc[j]);
}

// ---------------------------------------------------------------------------
// Kernel 4: Mq[b] = M[b] @ Wq   (Wq = w_qkv rows [0,256), bf16 in g_wq)
//   Mq[b][o][c] = sum_{c'} M[b][o][c'] * Wq[c'][c]
// 128x64 tiles, K=256, cp.async double-buffered. grid (4, 2, 16).
// ---------------------------------------------------------------------------
__global__ __launch_bounds__(256, 2) void k_mq() {
    __shared__ __nv_bfloat16 As[2][128][40];   // [o][c']
    __shared__ __nv_bfloat16 Bs[2][32][72];    // [c'][c]

    const int b  = blockIdx.z;
    const int o0 = blockIdx.y * 128;
    const int n0 = blockIdx.x * 64;
    const __nv_bfloat16* Ma = g_M  + (size_t)b * CDIM * CDIM;
    __nv_bfloat16*       Cb = g_Mq + (size_t)b * CDIM * CDIM;

    const int tid  = threadIdx.x;
    const int lane = tid & 31;
    const int wid  = tid >> 5;
    const int wm0  = (wid & 3) * 32;
    const int wn0  = (wid >> 2) * 32;

    const int aR0 = tid >> 2,          aC0 = (tid & 3) * 8;
    const int aR1 = (tid + 256) >> 2,  aC1 = ((tid + 256) & 3) * 8;
    const int bR  = tid >> 3,          bC  = (tid & 7) * 8;
    const __nv_bfloat16* aS0 = &Ma[(size_t)(o0 + aR0) * CDIM + aC0];
    const __nv_bfloat16* aS1 = &Ma[(size_t)(o0 + aR1) * CDIM + aC1];
    const __nv_bfloat16* bS  = &g_wq[(size_t)bR * CDIM + n0 + bC];

    auto stage = [&](int buf, int c0) {
        cp16(cvta_s(&As[buf][aR0][aC0]), aS0 + c0);
        cp16(cvta_s(&As[buf][aR1][aC1]), aS1 + c0);
        cp16(cvta_s(&Bs[buf][bR][bC]),   bS + (size_t)c0 * CDIM);
    };

    float acc[2][4][4] = {};

    stage(0, 0);
    CP_COMMIT();

    #pragma unroll
    for (int it = 0; it < 8; it++) {
        const int buf = it & 1;
        if (it < 7) { stage(buf ^ 1, (it + 1) * 32); CP_COMMIT(); }
        if (it < 7) { CP_WAIT(1); } else { CP_WAIT(0); }
        __syncthreads();

        #pragma unroll
        for (int kk = 0; kk < 32; kk += 16) {
            uint32_t a[2][4];
            #pragma unroll
            for (int mi = 0; mi < 2; mi++) {
                uint32_t ad = cvta_s(&As[buf][wm0 + mi * 16 + (lane & 15)][kk + (lane >> 4) * 8]);
                LDSM_X4(a[mi][0], a[mi][1], a[mi][2], a[mi][3], ad);
            }
            uint32_t bfr[4][2];
            #pragma unroll
            for (int np = 0; np < 2; np++) {
                uint32_t ad = cvta_s(&Bs[buf][kk + ((lane >> 3) & 1) * 8 + (lane & 7)]
                                            [wn0 + np * 16 + (lane >> 4) * 8]);
                uint32_t r0, r1, r2, r3;
                LDSM_X4_T(r0, r1, r2, r3, ad);
                bfr[2*np][0] = r0; bfr[2*np][1] = r1;
                bfr[2*np+1][0] = r2; bfr[2*np+1][1] = r3;
            }
            #pragma unroll
            for (int mi = 0; mi < 2; mi++)
                #pragma unroll
                for (int ni = 0; ni < 4; ni++)
                    MMA_BF16(acc[mi][ni], a[mi], bfr[ni][0], bfr[ni][1]);
        }
        __syncthreads();
    }

    #pragma unroll
    for (int mi = 0; mi < 2; mi++) {
        int r0 = o0 + wm0 + mi * 16 + (lane >> 2);
        #pragma unroll
        for (int ni = 0; ni < 4; ni++) {
            int cc = n0 + wn0 + ni * 8 + (lane & 3) * 2;
            __nv_bfloat162 v0, v1;
            v0.x = __float2bfloat16_rn(acc[mi][ni][0]);
            v0.y = __float2bfloat16_rn(acc[mi][ni][1]);
            v1.x = __float2bfloat16_rn(acc[mi][ni][2]);
            v1.y = __float2bfloat16_rn(acc[mi][ni][3]);
            *(__nv_bfloat162*)&Cb[(size_t)r0 * CDIM + cc]       = v0;
            *(__nv_bfloat162*)&Cb[(size_t)(r0 + 8) * CDIM + cc] = v1;
        }
    }
}

// ---------------------------------------------------------------------------
// Kernel 5: y[b,o,n] = sum_c Mq[b][o][c]*xb[b,c,n] + gamma[o]*b_out[o] + x[b,o,n]
// bf16 HMMA, cp.async double-buffered, fused fp32 epilogue
// ---------------------------------------------------------------------------
__global__ __launch_bounds__(256, 2) void k_out(const float* __restrict__ X,
                                                const float* __restrict__ b_out,
                                                const float* __restrict__ gamma,
                                                float* __restrict__ Y) {
    __shared__ __nv_bfloat16 As[2][128][40];
    __shared__ __nv_bfloat16 Bs[2][32][136];

    const int b  = blockIdx.z;
    const int o0 = blockIdx.y * 128;
    const int n0 = blockIdx.x * 128;
    const __nv_bfloat16* Mb = g_Mq + (size_t)b * CDIM * CDIM;
    const __nv_bfloat16* Qb = g_xb + (size_t)b * CDIM * NPix;
    const float* Xb = X + (size_t)b * CDIM * NPix;
    float*       Yb = Y + (size_t)b * CDIM * NPix;

    const int tid  = threadIdx.x;
    const int lane = tid & 31;
    const int wid  = tid >> 5;
    const int wm0  = (wid & 3) * 32;
    const int wn0  = (wid >> 2) * 64;

    const int aR0 = tid >> 2,          aC0 = (tid & 3) * 8;
    const int aR1 = (tid + 256) >> 2,  aC1 = ((tid + 256) & 3) * 8;
    const int bR0 = tid >> 4,          bC0 = (tid & 15) * 8;
    const int bR1 = (tid + 256) >> 4,  bC1 = ((tid + 256) & 15) * 8;
    const __nv_bfloat16* aS0 = &Mb[(size_t)(o0 + aR0) * CDIM + aC0];
    const __nv_bfloat16* aS1 = &Mb[(size_t)(o0 + aR1) * CDIM + aC1];
    const __nv_bfloat16* bS0 = &Qb[(size_t)bR0 * NPix + n0 + bC0];
    const __nv_bfloat16* bS1 = &Qb[(size_t)bR1 * NPix + n0 + bC1];

    auto stage = [&](int buf, int c0) {
        cp16(cvta_s(&As[buf][aR0][aC0]), aS0 + c0);
        cp16(cvta_s(&As[buf][aR1][aC1]), aS1 + c0);
        cp16(cvta_s(&Bs[buf][bR0][bC0]), bS0 + (size_t)c0 * NPix);
        cp16(cvta_s(&Bs[buf][bR1][bC1]), bS1 + (size_t)c0 * NPix);
    };

    float acc[2][8][4] = {};

    stage(0, 0);
    CP_COMMIT();

    #pragma unroll
    for (int it = 0; it < 8; it++) {
        const int buf = it & 1;
        if (it < 7) { stage(buf ^ 1, (it + 1) * 32); CP_COMMIT(); }
        if (it < 7) { CP_WAIT(1); } else { CP_WAIT(0); }
        __syncthreads();

        #pragma unroll
        for (int kk = 0; kk < 32; kk += 16) {
            uint32_t a[2][4];
            #pragma unroll
            for (int mi = 0; mi < 2; mi++) {
                uint32_t ad = cvta_s(&As[buf][wm0 + mi * 16 + (lane & 15)][kk + (lane >> 4) * 8]);
                LDSM_X4(a[mi][0], a[mi][1], a[mi][2], a[mi][3], ad);
            }
            uint32_t bfr[8][2];
            #pragma unroll
            for (int np = 0; np < 4; np++) {
                uint32_t ad = cvta_s(&Bs[buf][kk + ((lane >> 3) & 1) * 8 + (lane & 7)]
                                            [wn0 + np * 16 + (lane >> 4) * 8]);
                uint32_t r0, r1, r2, r3;
                LDSM_X4_T(r0, r1, r2, r3, ad);
                bfr[2*np][0] = r0; bfr[2*np][1] = r1;
                bfr[2*np+1][0] = r2; bfr[2*np+1][1] = r3;
            }
            #pragma unroll
            for (int mi = 0; mi < 2; mi++)
                #pragma unroll
                for (int ni = 0; ni < 8; ni++)
                    MMA_BF16(acc[mi][ni], a[mi], bfr[ni][0], bfr[ni][1]);
        }
        __syncthreads();
    }

    #pragma unroll
    for (int mi = 0; mi < 2; mi++) {
        int r0 = o0 + wm0 + mi * 16 + (lane >> 2);
        int r1 = r0 + 8;
        float bias0 = gamma[r0] * b_out[r0];
        float bias1 = gamma[r1] * b_out[r1];
        #pragma unroll
        for (int ni = 0; ni < 8; ni++) {
            int cc = n0 + wn0 + ni * 8 + (lane & 3) * 2;
            size_t off0 = (size_t)r0 * NPix + cc;
            size_t off1 = (size_t)r1 * NPix + cc;
            float2 x0 = *(const float2*)&Xb[off0];
            float2 x1 = *(const float2*)&Xb[off1];
            float2 y0 = make_float2(acc[mi][ni][0] + bias0 + x0.x,
                                    acc[mi][ni][1] + bias0 + x0.y);
            float2 y1 = make_float2(acc[mi][ni][2] + bias1 + x1.x,
                                    acc[mi][ni][3] + bias1 + x1.y);
            *(float2*)&Yb[off0] = y0;
            *(float2*)&Yb[off1] = y1;
        }
    }
}

// ---------------------------------------------------------------------------
extern "C" void kernel_launch(void* const* d_in, const int* in_sizes, int n_in,
                              void* d_out, int out_size) {
    const float* x      = (const float*)d_in[0];
    const float* w_qkv  = (const float*)d_in[1];
    const float* w_out  = (const float*)d_in[2];
    const float* b_out  = (const float*)d_in[3];
    const float* gamma  = (const float*)d_in[4];
    float* y = (float*)d_out;

    k_cvt_x<<<(BATCH * CDIM * NPix) / 1024, 256>>>(x);
    k_cvt_w<<<(O3 * CDIM) / 1024, 256>>>(w_qkv);
    k_qkv<<<dim3(NPix / 128, (O3 - CDIM) / 128, BATCH), 256>>>();
    k_ctx<<<dim3(NSPLIT, BATCH * HEADS), 256>>>();
    k_mix<<<dim3(BATCH * HEADS, 4), 256>>>(w_out, gamma);
    k_mq<<<dim3(CDIM / 64, CDIM / 128, BATCH), 256>>>();
    k_out<<<dim3(NPix / 128, CDIM / 128, BATCH), 256>>>(x, b_out, gamma, y);
}